// round 1
// baseline (speedup 1.0000x reference)
#include <cuda_runtime.h>
#include <cstdint>

// Problem constants
// x: [2][4][8][8][8][96][96] f32, W: [9][4][4][3][3][3] f32, b: [9][4] f32
// out: [2][4][6][6][8][96][96] f32
#define HW_PLANE (96*96)      // 9216

__device__ __forceinline__ void cp_async4(uint32_t saddr, const void* gsrc, int srcsize) {
    asm volatile("cp.async.ca.shared.global [%0], [%1], 4, %2;\n"
                 :: "r"(saddr), "l"(gsrc), "r"(srcsize));
}
__device__ __forceinline__ void cp_commit() {
    asm volatile("cp.async.commit_group;\n" ::: "memory");
}
__device__ __forceinline__ void cp_wait1() {
    asm volatile("cp.async.wait_group 1;\n" ::: "memory");
}

// Block: 384 threads = 24 tx (4 cols each) x 16 ty (2 rows each)
// Tile: 32 output rows x 96 cols (full width), all 4 output channels.
// Iterations: 108 = ci(4) x ij(9) x kd(3), double-buffered input planes.
__global__ __launch_bounds__(384)
void conv5d_kernel(const float* __restrict__ x,
                   const float* __restrict__ Wg,
                   const float* __restrict__ bg,
                   float* __restrict__ out)
{
    __shared__ float wsh[3888];          // [(ci*9+ij)*3+kd][tap(9)][o(4)]
    __shared__ float tile[2][34 * 100];  // 34 rows, 98 used cols, stride 100
    __shared__ float mbsh[4];

    const int tid   = threadIdx.x;
    const int htile = blockIdx.x % 3;
    const int d     = blockIdx.x / 3;
    const int t     = blockIdx.y;
    const int c     = blockIdx.z % 6;
    const int b     = blockIdx.z / 6;
    const int h0    = htile * 32;

    // ---- stage weights transposed: wsh[n*36 + (kh*3+kw)*4 + o], n = (ci*9+ij)*3+kd
    for (int idx = tid; idx < 3888; idx += 384) {
        int o   = idx & 3;
        int tap = (idx >> 2) % 9;
        int kd  = (idx / 36) % 3;
        int ij  = (idx / 108) % 9;
        int ci  = idx / 972;
        int kh = tap / 3, kw = tap - kh * 3;
        wsh[idx] = Wg[((ij * 4 + o) * 4 + ci) * 27 + kd * 9 + kh * 3 + kw];
    }
    if (tid < 4) {
        float s = 0.f;
        #pragma unroll
        for (int ij = 0; ij < 9; ij++) s += bg[ij * 4 + tid];
        mbsh[tid] = s * (1.0f / 9.0f);
    }

    // ---- per-thread tile-load slots (iteration-invariant)
    int so[9];          // smem offsets (floats), -1 = unused
    int go[9];          // global plane offsets
    unsigned vm = 0;    // h/w validity mask
    #pragma unroll
    for (int e = 0; e < 9; e++) {
        int idx = tid + e * 384;
        if (idx < 34 * 98) {
            int row = idx / 98;
            int col = idx - row * 98;
            int h = h0 - 1 + row;
            int w = col - 1;
            bool v = (h >= 0 && h < 96 && w >= 0 && w < 96);
            so[e] = row * 100 + col;
            go[e] = v ? (h * 96 + w) : 0;
            if (v) vm |= (1u << e);
        } else {
            so[e] = -1;
        }
    }

    const float* xb = x + (size_t)b * (4 * 8 * 8 * 8 * HW_PLANE);

    auto issue = [&](int n) {
        int ci  = n / 27;
        int rem = n - ci * 27;
        int ij  = rem / 3;
        int kd  = rem - ij * 3;
        int i = ij / 3, j = ij - i * 3;
        int dz = d + kd - 1;
        bool dv = (dz >= 0) && (dz < 8);
        const float* plane = xb +
            (size_t)(((ci * 8 + (c + i)) * 8 + (t + j)) * 8 + (dv ? dz : 0)) * HW_PLANE;
        uint32_t sbase = (uint32_t)__cvta_generic_to_shared(tile[n & 1]);
        #pragma unroll
        for (int e = 0; e < 9; e++) {
            if (so[e] >= 0) {
                int sz = (dv && ((vm >> e) & 1u)) ? 4 : 0;
                cp_async4(sbase + (uint32_t)so[e] * 4u, plane + go[e], sz);
            }
        }
    };

    float4 acc[2][4];
    #pragma unroll
    for (int py = 0; py < 2; py++)
        #pragma unroll
        for (int px = 0; px < 4; px++)
            acc[py][px] = make_float4(0.f, 0.f, 0.f, 0.f);

    issue(0);
    cp_commit();

    const int tx = tid % 24;
    const int ty = tid / 24;

    for (int n = 0; n < 108; n++) {
        if (n < 107) issue(n + 1);
        cp_commit();
        cp_wait1();              // buffer for iteration n is complete
        __syncthreads();

        // weights for this iteration: 9 taps x 4 o, as 9x LDS.128
        const float* wb = &wsh[n * 36];
        float4 wv[9];
        #pragma unroll
        for (int tp = 0; tp < 9; tp++)
            wv[tp] = *reinterpret_cast<const float4*>(wb + tp * 4);

        // input rows: 4 rows x 6 cols per thread
        const float* tb = &tile[n & 1][ty * 200 + tx * 4];
        float r[4][6];
        #pragma unroll
        for (int rr = 0; rr < 4; rr++) {
            float4 a  = *reinterpret_cast<const float4*>(tb + rr * 100);
            float2 b2 = *reinterpret_cast<const float2*>(tb + rr * 100 + 4);
            r[rr][0] = a.x; r[rr][1] = a.y; r[rr][2] = a.z; r[rr][3] = a.w;
            r[rr][4] = b2.x; r[rr][5] = b2.y;
        }

        #pragma unroll
        for (int kh = 0; kh < 3; kh++)
            #pragma unroll
            for (int kw = 0; kw < 3; kw++) {
                float4 wt = wv[kh * 3 + kw];
                #pragma unroll
                for (int py = 0; py < 2; py++)
                    #pragma unroll
                    for (int px = 0; px < 4; px++) {
                        float xv = r[py + kh][kw + px];
                        acc[py][px].x = fmaf(xv, wt.x, acc[py][px].x);
                        acc[py][px].y = fmaf(xv, wt.y, acc[py][px].y);
                        acc[py][px].z = fmaf(xv, wt.z, acc[py][px].z);
                        acc[py][px].w = fmaf(xv, wt.w, acc[py][px].w);
                    }
            }
        __syncthreads();         // protect tile[n&1] before it is refilled at n+1
    }

    // ---- epilogue: out[b][o][c][t][d][h][w]
    const float invn = 1.0f / 9.0f;
    const float mb0 = mbsh[0], mb1 = mbsh[1], mb2 = mbsh[2], mb3 = mbsh[3];
    size_t ob = ((((size_t)(b * 4) * 6 + c) * 6 + t) * 8 + d) * (size_t)HW_PLANE;
    const size_t ostride = (size_t)6 * 6 * 8 * HW_PLANE;   // per-o stride

    #pragma unroll
    for (int py = 0; py < 2; py++) {
        int h = h0 + ty * 2 + py;
        size_t rowoff = ob + (size_t)h * 96 + tx * 4;
        float4 v;
        v = make_float4(fmaf(acc[py][0].x, invn, mb0), fmaf(acc[py][1].x, invn, mb0),
                        fmaf(acc[py][2].x, invn, mb0), fmaf(acc[py][3].x, invn, mb0));
        *reinterpret_cast<float4*>(out + rowoff) = v;
        v = make_float4(fmaf(acc[py][0].y, invn, mb1), fmaf(acc[py][1].y, invn, mb1),
                        fmaf(acc[py][2].y, invn, mb1), fmaf(acc[py][3].y, invn, mb1));
        *reinterpret_cast<float4*>(out + rowoff + ostride) = v;
        v = make_float4(fmaf(acc[py][0].z, invn, mb2), fmaf(acc[py][1].z, invn, mb2),
                        fmaf(acc[py][2].z, invn, mb2), fmaf(acc[py][3].z, invn, mb2));
        *reinterpret_cast<float4*>(out + rowoff + 2 * ostride) = v;
        v = make_float4(fmaf(acc[py][0].w, invn, mb3), fmaf(acc[py][1].w, invn, mb3),
                        fmaf(acc[py][2].w, invn, mb3), fmaf(acc[py][3].w, invn, mb3));
        *reinterpret_cast<float4*>(out + rowoff + 3 * ostride) = v;
    }
}

extern "C" void kernel_launch(void* const* d_in, const int* in_sizes, int n_in,
                              void* d_out, int out_size) {
    const float* x  = (const float*)d_in[0];
    const float* Wg = (const float*)d_in[1];
    const float* bg = (const float*)d_in[2];
    float* out = (float*)d_out;

    dim3 grid(24, 6, 12);   // x: htile(3) + 3*d(8); y: t(6); z: b*6+c(12)
    dim3 block(384);
    conv5d_kernel<<<grid, block>>>(x, Wg, bg, out);
}

// round 2
// speedup vs baseline: 1.3824x; 1.3824x over previous
#include <cuda_runtime.h>
#include <cstdint>

// x: [2][4][8][8][8][96][96] f32, W: [9][4][4][3][3][3] f32, b: [9][4] f32
// out: [2][4][6][6][8][96][96] f32
#define HW_PLANE 9216
typedef unsigned long long u64;

__device__ __forceinline__ void cp_async16(uint32_t saddr, const void* g, int srcsize) {
    asm volatile("cp.async.cg.shared.global [%0], [%1], 16, %2;\n"
                 :: "r"(saddr), "l"(g), "r"(srcsize));
}
__device__ __forceinline__ void cp_commit() {
    asm volatile("cp.async.commit_group;\n" ::: "memory");
}
__device__ __forceinline__ void cp_wait1() {
    asm volatile("cp.async.wait_group 1;\n" ::: "memory");
}
__device__ __forceinline__ u64 pack2(float lo, float hi) {
    u64 r; asm("mov.b64 %0, {%1, %2};" : "=l"(r) : "f"(lo), "f"(hi)); return r;
}
__device__ __forceinline__ void ffma2(u64& a, u64 x, u64 w) {
    asm("fma.rn.f32x2 %0, %1, %2, %0;" : "+l"(a) : "l"(x), "l"(w));
}
__device__ __forceinline__ float2 unpack2(u64 v) {
    float lo, hi; asm("mov.b64 {%0, %1}, %2;" : "=f"(lo), "=f"(hi) : "l"(v));
    return make_float2(lo, hi);
}

// Block: 384 threads = 24 tx (4 cols) x 16 ty (2 rows). Tile 32 rows x 96 cols, 4 o-chans.
// 108 iters = ci(4) x ij(9) x kd(3), triple-buffered input planes, f32x2-packed FMAs.
__global__ __launch_bounds__(384)
void conv5d_kernel(const float* __restrict__ x,
                   const float* __restrict__ Wg,
                   const float* __restrict__ bg,
                   float* __restrict__ out)
{
    __shared__ __align__(16) float wsh[3888];          // [n(108)][tap(9)][o(4)]
    __shared__ __align__(16) float tile[3][34 * 104];  // row: [pad3][w=-1][w0..95][w=96][pad3]
    __shared__ float mbsh[4];

    const int tid   = threadIdx.x;
    const int htile = blockIdx.x % 3;
    const int d     = blockIdx.x / 3;
    const int t     = blockIdx.y;
    const int c     = blockIdx.z % 6;
    const int b     = blockIdx.z / 6;
    const int h0    = htile * 32;

    // ---- stage weights: wsh[n*36 + tap*4 + o], n = (ci*9+ij)*3+kd
    for (int idx = tid; idx < 3888; idx += 384) {
        int o   = idx & 3;
        int tap = (idx >> 2) % 9;
        int kd  = (idx / 36) % 3;
        int ij  = (idx / 108) % 9;
        int ci  = idx / 972;
        int kh = tap / 3, kw = tap - kh * 3;
        wsh[idx] = Wg[((ij * 4 + o) * 4 + ci) * 27 + kd * 9 + kh * 3 + kw];
    }
    if (tid < 4) {
        float s = 0.f;
        #pragma unroll
        for (int ij = 0; ij < 9; ij++) s += bg[ij * 4 + tid];
        mbsh[tid] = s * (1.0f / 9.0f);
    }
    // halo columns (w=-1, w=96) are conv zero-padding: zero once, never loaded
    if (tid < 102) {  // 3 bufs x 34 rows
        int buf = tid / 34, row = tid - buf * 34;
        tile[buf][row * 104 + 3]   = 0.f;
        tile[buf][row * 104 + 100] = 0.f;
    }

    // ---- per-thread interior load slots (16B each): 34 rows x 24 quads = 816
    int   mso[3];     // smem float offset, -1 unused
    int   mgo[3];     // global plane offset
    int   msz[3];     // 16 if h valid else 0
    #pragma unroll
    for (int e = 0; e < 3; e++) {
        int idx = tid + e * 384;
        if (idx < 816) {
            int row = idx / 24;
            int q   = idx - row * 24;
            int h   = h0 - 1 + row;
            bool hv = (h >= 0 && h < 96);
            mso[e] = row * 104 + 4 + q * 4;
            mgo[e] = (hv ? h : 0) * 96 + q * 4;
            msz[e] = hv ? 16 : 0;
        } else {
            mso[e] = -1;
        }
    }

    uint32_t sb0 = (uint32_t)__cvta_generic_to_shared(tile[0]);
    uint32_t sb1 = (uint32_t)__cvta_generic_to_shared(tile[1]);
    uint32_t sb2 = (uint32_t)__cvta_generic_to_shared(tile[2]);

    // ---- issue-side state machine over (ci, i, j, kd)
    const float* xb = x + (size_t)b * (4 * 8 * 8 * 8 * HW_PLANE);
    const float* bcur = xb + ((size_t)((c * 8 + t) * 8) + (d - 1)) * HW_PLANE; // (ci=0,i=0,j=0), dz=d-1
    int kd_m = 0, jj = 0, ii = 0;
    int ibuf = 0;
    const bool dval0 = (d >= 1), dval2 = (d <= 6);

    auto issue_next = [&]() {
        bool dv = (kd_m == 0) ? dval0 : ((kd_m == 2) ? dval2 : true);
        const float* plane = dv ? (bcur + (size_t)kd_m * HW_PLANE) : (bcur + HW_PLANE);
        uint32_t sbase = (ibuf == 0) ? sb0 : ((ibuf == 1) ? sb1 : sb2);
        #pragma unroll
        for (int e = 0; e < 3; e++) {
            if (mso[e] >= 0)
                cp_async16(sbase + (uint32_t)mso[e] * 4u, plane + mgo[e], dv ? msz[e] : 0);
        }
        // advance (ci,i,j,kd) and rotating buffer
        kd_m++;
        if (kd_m == 3) {
            kd_m = 0;
            long step = 8;                      // j++
            jj++;
            if (jj == 3) { jj = 0; ii++; step = 48;          // i++, j reset
                if (ii == 3) { ii = 0; step = 368; } }       // ci++, i,j reset
            bcur += step * (long)HW_PLANE;
        }
        ibuf = (ibuf == 2) ? 0 : ibuf + 1;
    };

    // accumulators: o0,o1 pair and o2,o3 pair per pixel
    u64 a01[2][4], a23[2][4];
    #pragma unroll
    for (int py = 0; py < 2; py++)
        #pragma unroll
        for (int px = 0; px < 4; px++) { a01[py][px] = 0ull; a23[py][px] = 0ull; }

    issue_next(); cp_commit();
    issue_next(); cp_commit();

    const int tx = tid % 24;
    const int ty = tid / 24;
    int cbuf = 0;

    for (int n = 0; n < 108; n++) {
        cp_wait1();              // all but most recent group done -> data n arrived
        __syncthreads();         // all threads' group-n visible; prev compute done
        if (n < 106) issue_next();
        cp_commit();             // always commit (possibly empty) to keep counts

        // load + duplicate-pack input rows: 4 rows x 6 cols
        const float* tb = &tile[cbuf][(ty * 2) * 104];
        u64 rp[4][6];
        #pragma unroll
        for (int rr = 0; rr < 4; rr++) {
            const float* rw = tb + rr * 104;
            float  lv = rw[3 + tx * 4];
            float4 m  = *reinterpret_cast<const float4*>(rw + 4 + tx * 4);
            float  rv = rw[8 + tx * 4];
            rp[rr][0] = pack2(lv,  lv);
            rp[rr][1] = pack2(m.x, m.x);
            rp[rr][2] = pack2(m.y, m.y);
            rp[rr][3] = pack2(m.z, m.z);
            rp[rr][4] = pack2(m.w, m.w);
            rp[rr][5] = pack2(rv,  rv);
        }

        const ulonglong2* wb = reinterpret_cast<const ulonglong2*>(&wsh[n * 36]);
        #pragma unroll
        for (int kh = 0; kh < 3; kh++)
            #pragma unroll
            for (int kw = 0; kw < 3; kw++) {
                ulonglong2 w2 = wb[kh * 3 + kw];   // (o0,o1),(o2,o3)
                #pragma unroll
                for (int py = 0; py < 2; py++)
                    #pragma unroll
                    for (int px = 0; px < 4; px++) {
                        u64 xv = rp[py + kh][kw + px];
                        ffma2(a01[py][px], xv, w2.x);
                        ffma2(a23[py][px], xv, w2.y);
                    }
            }

        cbuf = (cbuf == 2) ? 0 : cbuf + 1;
    }

    // ---- epilogue
    const float invn = 1.0f / 9.0f;
    size_t ob = ((((size_t)(b * 4) * 6 + c) * 6 + t) * 8 + d) * (size_t)HW_PLANE;
    const size_t ostride = (size_t)6 * 6 * 8 * HW_PLANE;

    #pragma unroll
    for (int py = 0; py < 2; py++) {
        int h = h0 + ty * 2 + py;
        size_t rowoff = ob + (size_t)h * 96 + tx * 4;
        float v0[4], v1[4], v2[4], v3[4];
        #pragma unroll
        for (int px = 0; px < 4; px++) {
            float2 p01 = unpack2(a01[py][px]);
            float2 p23 = unpack2(a23[py][px]);
            v0[px] = p01.x; v1[px] = p01.y; v2[px] = p23.x; v3[px] = p23.y;
        }
        float4 w4;
        w4 = make_float4(fmaf(v0[0], invn, mbsh[0]), fmaf(v0[1], invn, mbsh[0]),
                         fmaf(v0[2], invn, mbsh[0]), fmaf(v0[3], invn, mbsh[0]));
        *reinterpret_cast<float4*>(out + rowoff) = w4;
        w4 = make_float4(fmaf(v1[0], invn, mbsh[1]), fmaf(v1[1], invn, mbsh[1]),
                         fmaf(v1[2], invn, mbsh[1]), fmaf(v1[3], invn, mbsh[1]));
        *reinterpret_cast<float4*>(out + rowoff + ostride) = w4;
        w4 = make_float4(fmaf(v2[0], invn, mbsh[2]), fmaf(v2[1], invn, mbsh[2]),
                         fmaf(v2[2], invn, mbsh[2]), fmaf(v2[3], invn, mbsh[2]));
        *reinterpret_cast<float4*>(out + rowoff + 2 * ostride) = w4;
        w4 = make_float4(fmaf(v3[0], invn, mbsh[3]), fmaf(v3[1], invn, mbsh[3]),
                         fmaf(v3[2], invn, mbsh[3]), fmaf(v3[3], invn, mbsh[3]));
        *reinterpret_cast<float4*>(out + rowoff + 3 * ostride) = w4;
    }
}

extern "C" void kernel_launch(void* const* d_in, const int* in_sizes, int n_in,
                              void* d_out, int out_size) {
    const float* x  = (const float*)d_in[0];
    const float* Wg = (const float*)d_in[1];
    const float* bg = (const float*)d_in[2];
    float* out = (float*)d_out;

    dim3 grid(24, 6, 12);   // x: htile(3) + 3*d(8); y: t(6); z: b*6+c(12)
    dim3 block(384);
    conv5d_kernel<<<grid, block>>>(x, Wg, bg, out);
}